// round 12
// baseline (speedup 1.0000x reference)
#include <cuda_runtime.h>
#include <cuda_fp16.h>

#define D_FEAT 64
#define N_MAX 100000

__device__ int g_row_ptr[N_MAX + 1];
// fp16 staged copy of x: N_MAX rows x 32 half2 (64 features). 12.8MB scratch.
__device__ __half2 g_xh[N_MAX * 32];

// Kernel A: boundary scatter (row sorted).
__global__ void build_row_ptr_scatter(const int* __restrict__ row, int n, int E) {
    int i = blockIdx.x * blockDim.x + threadIdx.x;
    if (i > E) return;
    if (i == 0) {
        int r0 = __ldg(&row[0]);
        for (int r = 0; r <= r0; r++) g_row_ptr[r] = 0;
    } else if (i == E) {
        int rp = __ldg(&row[E - 1]);
        for (int r = rp + 1; r <= n; r++) g_row_ptr[r] = E;
    } else {
        int rc = __ldg(&row[i]);
        int rp = __ldg(&row[i - 1]);
        for (int r = rp + 1; r <= rc; r++) g_row_ptr[r] = i;
    }
}

// Kernel C: stream-convert x (fp32) -> g_xh (fp16). Fully coalesced.
__global__ void convert_x_half(const float4* __restrict__ x, int n4) {
    int i = blockIdx.x * blockDim.x + threadIdx.x;
    if (i >= n4) return;
    float4 v = __ldg(&x[i]);
    g_xh[2 * i + 0] = __floats2half2_rn(v.x, v.y);
    g_xh[2 * i + 1] = __floats2half2_rn(v.z, v.w);
}

// Kernel B: one warp per row, lane owns features {2l,2l+1} as ONE half2.
// Gather = LDG.32: 128B/warp = 1 cache line = 1 L1 wavefront per edge
// (half the fp32 version's gather work). Accumulate in fp32.
__global__ void __launch_bounds__(128)
spmm_mean_warp_per_row(const float* __restrict__ vals,
                       const int* __restrict__ col,
                       float* __restrict__ out,
                       int n) {
    int warp_id = (blockIdx.x * blockDim.x + threadIdx.x) >> 5;
    int lane = threadIdx.x & 31;
    if (warp_id >= n) return;

    int s = g_row_ptr[warp_id];
    int e = g_row_ptr[warp_id + 1];

    const __half2* xh = g_xh + lane;
    float2 a0 = make_float2(0.f, 0.f);
    float2 a1 = make_float2(0.f, 0.f);

    int i = s;

    // Main loop: 8 edges, 8 independent 1-line gathers in flight.
    for (; i + 8 <= e; i += 8) {
        int c0 = __ldg(&col[i + 0]);
        int c1 = __ldg(&col[i + 1]);
        int c2 = __ldg(&col[i + 2]);
        int c3 = __ldg(&col[i + 3]);
        int c4 = __ldg(&col[i + 4]);
        int c5 = __ldg(&col[i + 5]);
        int c6 = __ldg(&col[i + 6]);
        int c7 = __ldg(&col[i + 7]);
        __half2 h0 = xh[(size_t)c0 * 32];
        __half2 h1 = xh[(size_t)c1 * 32];
        __half2 h2 = xh[(size_t)c2 * 32];
        __half2 h3 = xh[(size_t)c3 * 32];
        __half2 h4 = xh[(size_t)c4 * 32];
        __half2 h5 = xh[(size_t)c5 * 32];
        __half2 h6 = xh[(size_t)c6 * 32];
        __half2 h7 = xh[(size_t)c7 * 32];
        float v0 = __ldg(&vals[i + 0]);
        float v1 = __ldg(&vals[i + 1]);
        float v2 = __ldg(&vals[i + 2]);
        float v3 = __ldg(&vals[i + 3]);
        float v4 = __ldg(&vals[i + 4]);
        float v5 = __ldg(&vals[i + 5]);
        float v6 = __ldg(&vals[i + 6]);
        float v7 = __ldg(&vals[i + 7]);
        float2 x0 = __half22float2(h0);
        float2 x1 = __half22float2(h1);
        float2 x2 = __half22float2(h2);
        float2 x3 = __half22float2(h3);
        float2 x4 = __half22float2(h4);
        float2 x5 = __half22float2(h5);
        float2 x6 = __half22float2(h6);
        float2 x7 = __half22float2(h7);
        a0.x = fmaf(v0, x0.x, a0.x); a0.y = fmaf(v0, x0.y, a0.y);
        a1.x = fmaf(v1, x1.x, a1.x); a1.y = fmaf(v1, x1.y, a1.y);
        a0.x = fmaf(v2, x2.x, a0.x); a0.y = fmaf(v2, x2.y, a0.y);
        a1.x = fmaf(v3, x3.x, a1.x); a1.y = fmaf(v3, x3.y, a1.y);
        a0.x = fmaf(v4, x4.x, a0.x); a0.y = fmaf(v4, x4.y, a0.y);
        a1.x = fmaf(v5, x5.x, a1.x); a1.y = fmaf(v5, x5.y, a1.y);
        a0.x = fmaf(v6, x6.x, a0.x); a0.y = fmaf(v6, x6.y, a0.y);
        a1.x = fmaf(v7, x7.x, a1.x); a1.y = fmaf(v7, x7.y, a1.y);
    }

    // Secondary: 4 edges.
    for (; i + 4 <= e; i += 4) {
        int c0 = __ldg(&col[i + 0]);
        int c1 = __ldg(&col[i + 1]);
        int c2 = __ldg(&col[i + 2]);
        int c3 = __ldg(&col[i + 3]);
        __half2 h0 = xh[(size_t)c0 * 32];
        __half2 h1 = xh[(size_t)c1 * 32];
        __half2 h2 = xh[(size_t)c2 * 32];
        __half2 h3 = xh[(size_t)c3 * 32];
        float v0 = __ldg(&vals[i + 0]);
        float v1 = __ldg(&vals[i + 1]);
        float v2 = __ldg(&vals[i + 2]);
        float v3 = __ldg(&vals[i + 3]);
        float2 x0 = __half22float2(h0);
        float2 x1 = __half22float2(h1);
        float2 x2 = __half22float2(h2);
        float2 x3 = __half22float2(h3);
        a0.x = fmaf(v0, x0.x, a0.x); a0.y = fmaf(v0, x0.y, a0.y);
        a1.x = fmaf(v1, x1.x, a1.x); a1.y = fmaf(v1, x1.y, a1.y);
        a0.x = fmaf(v2, x2.x, a0.x); a0.y = fmaf(v2, x2.y, a0.y);
        a1.x = fmaf(v3, x3.x, a1.x); a1.y = fmaf(v3, x3.y, a1.y);
    }

    // Tail: <=3 scalar edges.
    for (; i < e; i++) {
        int   c = __ldg(&col[i]);
        float v = __ldg(&vals[i]);
        float2 xv = __half22float2(xh[(size_t)c * 32]);
        a0.x = fmaf(v, xv.x, a0.x);
        a0.y = fmaf(v, xv.y, a0.y);
    }

    int deg = e - s;
    float inv = 1.0f / (float)(deg > 0 ? deg : 1);
    float2 o = make_float2((a0.x + a1.x) * inv, (a0.y + a1.y) * inv);

    *reinterpret_cast<float2*>(&out[(size_t)warp_id * D_FEAT + 2 * lane]) = o;
}

extern "C" void kernel_launch(void* const* d_in, const int* in_sizes, int n_in,
                              void* d_out, int out_size) {
    const float* x    = (const float*)d_in[0];
    const float* vals = (const float*)d_in[1];
    const int*   row  = (const int*)d_in[2];
    const int*   col  = (const int*)d_in[3];
    float* out = (float*)d_out;

    int n = in_sizes[0] / D_FEAT;   // 100000
    int E = in_sizes[1];            // 1200000

    {
        int threads = 256;
        int blocks = (E + 1 + threads - 1) / threads;
        build_row_ptr_scatter<<<blocks, threads>>>(row, n, E);
    }
    {
        int n4 = n * D_FEAT / 4;    // 1.6M float4s
        int threads = 256;
        int blocks = (n4 + threads - 1) / threads;
        convert_x_half<<<blocks, threads>>>((const float4*)x, n4);
    }
    {
        int threads = 128;
        int rows_per_block = threads / 32;
        int blocks = (n + rows_per_block - 1) / rows_per_block;
        spmm_mean_warp_per_row<<<blocks, threads>>>(vals, col, out, n);
    }
}

// round 13
// speedup vs baseline: 1.0626x; 1.0626x over previous
#include <cuda_runtime.h>
#include <cuda_fp16.h>

#define D_FEAT 64
#define N_MAX 100000

__device__ int g_row_ptr[N_MAX + 1];
// fp16 staged copy of x: N_MAX rows x 32 half2 (64 features). 12.8MB scratch.
__device__ __half2 g_xh[N_MAX * 32];

// Kernel C: stream-convert x (fp32) -> g_xh (fp16). Bandwidth-bound.
__global__ void convert_x_half(const float4* __restrict__ x, int n4) {
    int i = blockIdx.x * blockDim.x + threadIdx.x;
    if (i >= n4) return;
    float4 v = __ldg(&x[i]);
    g_xh[2 * i + 0] = __floats2half2_rn(v.x, v.y);
    g_xh[2 * i + 1] = __floats2half2_rn(v.z, v.w);
}

// Kernel A: boundary scatter, 4 edges per thread (int4). row is sorted.
__global__ void build_row_ptr_scatter4(const int* __restrict__ row, int n, int E) {
    int i = 4 * (blockIdx.x * blockDim.x + threadIdx.x);
    if (i >= E) return;

    int r0, r1, r2, r3;
    if (i + 3 < E) {
        int4 r4 = __ldg(reinterpret_cast<const int4*>(row + i));  // i % 4 == 0
        r0 = r4.x; r1 = r4.y; r2 = r4.z; r3 = r4.w;
    } else {
        r0 = __ldg(&row[i]);
        r1 = (i + 1 < E) ? __ldg(&row[i + 1]) : r0;
        r2 = (i + 2 < E) ? __ldg(&row[i + 2]) : r1;
        r3 = (i + 3 < E) ? __ldg(&row[i + 3]) : r2;
    }
    int prev = (i == 0) ? -1 : __ldg(&row[i - 1]);

    int rr[4] = {r0, r1, r2, r3};
#pragma unroll
    for (int k = 0; k < 4; k++) {
        if (i + k < E) {
            for (int r = prev + 1; r <= rr[k]; r++) g_row_ptr[r] = i + k;
            prev = rr[k];
        }
    }
    if (i + 4 >= E) {  // this thread owns the last edge: close the tail
        for (int r = prev + 1; r <= n; r++) g_row_ptr[r] = E;
    }
}

// Kernel B: one warp per row, lane owns features {2l,2l+1} as ONE half2.
// Gather = 4B/lane -> 128B/warp = 1 cache line = 1 L1 wavefront per edge.
// Accumulate fp32.
__global__ void __launch_bounds__(128)
spmm_mean_warp_per_row(const float* __restrict__ vals,
                       const int* __restrict__ col,
                       float* __restrict__ out,
                       int n) {
    int warp_id = (blockIdx.x * blockDim.x + threadIdx.x) >> 5;
    int lane = threadIdx.x & 31;
    if (warp_id >= n) return;

    int s = g_row_ptr[warp_id];
    int e = g_row_ptr[warp_id + 1];

    const __half2* xh = g_xh + lane;
    float2 a0 = make_float2(0.f, 0.f);
    float2 a1 = make_float2(0.f, 0.f);

    int i = s;

    // Main loop: 8 edges, 8 independent 1-line gathers in flight.
    for (; i + 8 <= e; i += 8) {
        int c0 = __ldg(&col[i + 0]);
        int c1 = __ldg(&col[i + 1]);
        int c2 = __ldg(&col[i + 2]);
        int c3 = __ldg(&col[i + 3]);
        int c4 = __ldg(&col[i + 4]);
        int c5 = __ldg(&col[i + 5]);
        int c6 = __ldg(&col[i + 6]);
        int c7 = __ldg(&col[i + 7]);
        __half2 h0 = __ldg(&xh[(size_t)c0 * 32]);
        __half2 h1 = __ldg(&xh[(size_t)c1 * 32]);
        __half2 h2 = __ldg(&xh[(size_t)c2 * 32]);
        __half2 h3 = __ldg(&xh[(size_t)c3 * 32]);
        __half2 h4 = __ldg(&xh[(size_t)c4 * 32]);
        __half2 h5 = __ldg(&xh[(size_t)c5 * 32]);
        __half2 h6 = __ldg(&xh[(size_t)c6 * 32]);
        __half2 h7 = __ldg(&xh[(size_t)c7 * 32]);
        float v0 = __ldg(&vals[i + 0]);
        float v1 = __ldg(&vals[i + 1]);
        float v2 = __ldg(&vals[i + 2]);
        float v3 = __ldg(&vals[i + 3]);
        float v4 = __ldg(&vals[i + 4]);
        float v5 = __ldg(&vals[i + 5]);
        float v6 = __ldg(&vals[i + 6]);
        float v7 = __ldg(&vals[i + 7]);
        float2 x0 = __half22float2(h0);
        float2 x1 = __half22float2(h1);
        float2 x2 = __half22float2(h2);
        float2 x3 = __half22float2(h3);
        float2 x4 = __half22float2(h4);
        float2 x5 = __half22float2(h5);
        float2 x6 = __half22float2(h6);
        float2 x7 = __half22float2(h7);
        a0.x = fmaf(v0, x0.x, a0.x); a0.y = fmaf(v0, x0.y, a0.y);
        a1.x = fmaf(v1, x1.x, a1.x); a1.y = fmaf(v1, x1.y, a1.y);
        a0.x = fmaf(v2, x2.x, a0.x); a0.y = fmaf(v2, x2.y, a0.y);
        a1.x = fmaf(v3, x3.x, a1.x); a1.y = fmaf(v3, x3.y, a1.y);
        a0.x = fmaf(v4, x4.x, a0.x); a0.y = fmaf(v4, x4.y, a0.y);
        a1.x = fmaf(v5, x5.x, a1.x); a1.y = fmaf(v5, x5.y, a1.y);
        a0.x = fmaf(v6, x6.x, a0.x); a0.y = fmaf(v6, x6.y, a0.y);
        a1.x = fmaf(v7, x7.x, a1.x); a1.y = fmaf(v7, x7.y, a1.y);
    }

    // Secondary: 4 edges.
    for (; i + 4 <= e; i += 4) {
        int c0 = __ldg(&col[i + 0]);
        int c1 = __ldg(&col[i + 1]);
        int c2 = __ldg(&col[i + 2]);
        int c3 = __ldg(&col[i + 3]);
        __half2 h0 = __ldg(&xh[(size_t)c0 * 32]);
        __half2 h1 = __ldg(&xh[(size_t)c1 * 32]);
        __half2 h2 = __ldg(&xh[(size_t)c2 * 32]);
        __half2 h3 = __ldg(&xh[(size_t)c3 * 32]);
        float v0 = __ldg(&vals[i + 0]);
        float v1 = __ldg(&vals[i + 1]);
        float v2 = __ldg(&vals[i + 2]);
        float v3 = __ldg(&vals[i + 3]);
        float2 x0 = __half22float2(h0);
        float2 x1 = __half22float2(h1);
        float2 x2 = __half22float2(h2);
        float2 x3 = __half22float2(h3);
        a0.x = fmaf(v0, x0.x, a0.x); a0.y = fmaf(v0, x0.y, a0.y);
        a1.x = fmaf(v1, x1.x, a1.x); a1.y = fmaf(v1, x1.y, a1.y);
        a0.x = fmaf(v2, x2.x, a0.x); a0.y = fmaf(v2, x2.y, a0.y);
        a1.x = fmaf(v3, x3.x, a1.x); a1.y = fmaf(v3, x3.y, a1.y);
    }

    // Tail: <=3 scalar edges.
    for (; i < e; i++) {
        int   c = __ldg(&col[i]);
        float v = __ldg(&vals[i]);
        float2 xv = __half22float2(__ldg(&xh[(size_t)c * 32]));
        a0.x = fmaf(v, xv.x, a0.x);
        a0.y = fmaf(v, xv.y, a0.y);
    }

    int deg = e - s;
    float inv = 1.0f / (float)(deg > 0 ? deg : 1);
    float2 o = make_float2((a0.x + a1.x) * inv, (a0.y + a1.y) * inv);

    *reinterpret_cast<float2*>(&out[(size_t)warp_id * D_FEAT + 2 * lane]) = o;
}

extern "C" void kernel_launch(void* const* d_in, const int* in_sizes, int n_in,
                              void* d_out, int out_size) {
    const float* x    = (const float*)d_in[0];
    const float* vals = (const float*)d_in[1];
    const int*   row  = (const int*)d_in[2];
    const int*   col  = (const int*)d_in[3];
    float* out = (float*)d_out;

    int n = in_sizes[0] / D_FEAT;   // 100000
    int E = in_sizes[1];            // 1200000

    {
        int n4 = n * D_FEAT / 4;    // 1.6M float4s
        int threads = 512;
        int blocks = (n4 + threads - 1) / threads;
        convert_x_half<<<blocks, threads>>>((const float4*)x, n4);
    }
    {
        int nt = (E + 3) / 4;       // 300k threads
        int threads = 256;
        int blocks = (nt + threads - 1) / threads;
        build_row_ptr_scatter4<<<blocks, threads>>>(row, n, E);
    }
    {
        int threads = 128;
        int rows_per_block = threads / 32;
        int blocks = (n + rows_per_block - 1) / rows_per_block;
        spmm_mean_warp_per_row<<<blocks, threads>>>(vals, col, out, n);
    }
}

// round 14
// speedup vs baseline: 1.1111x; 1.0457x over previous
#include <cuda_runtime.h>
#include <cuda_fp16.h>

#define D_FEAT 64
#define N_MAX 100000
#define CONV_BLOCKS 1184   // 148 SMs x 8
#define PREP_THREADS 256

__device__ int g_row_ptr[N_MAX + 1];
// fp16 staged x: N_MAX rows x 16 uint2 (= 32 half2 = 64 features). 12.8MB.
__device__ uint2 g_xh2[N_MAX * 16];

__device__ __forceinline__ unsigned pack_h2(float a, float b) {
    __half2 h = __floats2half2_rn(a, b);
    return *reinterpret_cast<unsigned*>(&h);
}

// Fused prep: blocks [0, CONV_BLOCKS) convert x fp32->fp16 (grid-stride,
// 8B stores); remaining blocks build row_ptr via boundary scatter (4 edges
// per thread, int4 loads). The two halves are independent and overlap.
__global__ void __launch_bounds__(PREP_THREADS)
prep_kernel(const float4* __restrict__ x4, const int* __restrict__ row,
            int n4, int n, int E) {
    if (blockIdx.x < CONV_BLOCKS) {
        // ---- convert: x (float4 view) -> g_xh2 (uint2 = 4 halves) ----
        int stride = CONV_BLOCKS * PREP_THREADS;
        for (int i = blockIdx.x * PREP_THREADS + threadIdx.x; i < n4; i += stride) {
            float4 v = __ldg(&x4[i]);
            uint2 p;
            p.x = pack_h2(v.x, v.y);
            p.y = pack_h2(v.z, v.w);
            g_xh2[i] = p;
        }
    } else {
        // ---- builder: boundary scatter, 4 edges/thread ----
        int t = (blockIdx.x - CONV_BLOCKS) * PREP_THREADS + threadIdx.x;
        int i = 4 * t;
        if (i >= E) return;

        int r0, r1, r2, r3;
        if (i + 3 < E) {
            int4 r4 = __ldg(reinterpret_cast<const int4*>(row + i));
            r0 = r4.x; r1 = r4.y; r2 = r4.z; r3 = r4.w;
        } else {
            r0 = __ldg(&row[i]);
            r1 = (i + 1 < E) ? __ldg(&row[i + 1]) : r0;
            r2 = (i + 2 < E) ? __ldg(&row[i + 2]) : r1;
            r3 = (i + 3 < E) ? __ldg(&row[i + 3]) : r2;
        }
        int prev = (i == 0) ? -1 : __ldg(&row[i - 1]);

        int rr[4] = {r0, r1, r2, r3};
#pragma unroll
        for (int k = 0; k < 4; k++) {
            if (i + k < E) {
                for (int r = prev + 1; r <= rr[k]; r++) g_row_ptr[r] = i + k;
                prev = rr[k];
            }
        }
        if (i + 4 >= E) {
            for (int r = prev + 1; r <= n; r++) g_row_ptr[r] = E;
        }
    }
}

// SpMM: one warp per row, lane owns features {2l,2l+1} as ONE half2.
// 1 cache line / 1 L1 wavefront per edge gather; fp32 accumulation.
__global__ void __launch_bounds__(128)
spmm_mean_warp_per_row(const float* __restrict__ vals,
                       const int* __restrict__ col,
                       float* __restrict__ out,
                       int n) {
    int warp_id = (blockIdx.x * blockDim.x + threadIdx.x) >> 5;
    int lane = threadIdx.x & 31;
    if (warp_id >= n) return;

    int s = g_row_ptr[warp_id];
    int e = g_row_ptr[warp_id + 1];

    const __half2* xh = reinterpret_cast<const __half2*>(g_xh2) + lane;
    float2 a0 = make_float2(0.f, 0.f);
    float2 a1 = make_float2(0.f, 0.f);

    int i = s;

    // Main loop: 8 edges, 8 independent 1-line gathers in flight.
    for (; i + 8 <= e; i += 8) {
        int c0 = __ldg(&col[i + 0]);
        int c1 = __ldg(&col[i + 1]);
        int c2 = __ldg(&col[i + 2]);
        int c3 = __ldg(&col[i + 3]);
        int c4 = __ldg(&col[i + 4]);
        int c5 = __ldg(&col[i + 5]);
        int c6 = __ldg(&col[i + 6]);
        int c7 = __ldg(&col[i + 7]);
        __half2 h0 = __ldg(&xh[(size_t)c0 * 32]);
        __half2 h1 = __ldg(&xh[(size_t)c1 * 32]);
        __half2 h2 = __ldg(&xh[(size_t)c2 * 32]);
        __half2 h3 = __ldg(&xh[(size_t)c3 * 32]);
        __half2 h4 = __ldg(&xh[(size_t)c4 * 32]);
        __half2 h5 = __ldg(&xh[(size_t)c5 * 32]);
        __half2 h6 = __ldg(&xh[(size_t)c6 * 32]);
        __half2 h7 = __ldg(&xh[(size_t)c7 * 32]);
        float v0 = __ldg(&vals[i + 0]);
        float v1 = __ldg(&vals[i + 1]);
        float v2 = __ldg(&vals[i + 2]);
        float v3 = __ldg(&vals[i + 3]);
        float v4 = __ldg(&vals[i + 4]);
        float v5 = __ldg(&vals[i + 5]);
        float v6 = __ldg(&vals[i + 6]);
        float v7 = __ldg(&vals[i + 7]);
        float2 x0 = __half22float2(h0);
        float2 x1 = __half22float2(h1);
        float2 x2 = __half22float2(h2);
        float2 x3 = __half22float2(h3);
        float2 x4 = __half22float2(h4);
        float2 x5 = __half22float2(h5);
        float2 x6 = __half22float2(h6);
        float2 x7 = __half22float2(h7);
        a0.x = fmaf(v0, x0.x, a0.x); a0.y = fmaf(v0, x0.y, a0.y);
        a1.x = fmaf(v1, x1.x, a1.x); a1.y = fmaf(v1, x1.y, a1.y);
        a0.x = fmaf(v2, x2.x, a0.x); a0.y = fmaf(v2, x2.y, a0.y);
        a1.x = fmaf(v3, x3.x, a1.x); a1.y = fmaf(v3, x3.y, a1.y);
        a0.x = fmaf(v4, x4.x, a0.x); a0.y = fmaf(v4, x4.y, a0.y);
        a1.x = fmaf(v5, x5.x, a1.x); a1.y = fmaf(v5, x5.y, a1.y);
        a0.x = fmaf(v6, x6.x, a0.x); a0.y = fmaf(v6, x6.y, a0.y);
        a1.x = fmaf(v7, x7.x, a1.x); a1.y = fmaf(v7, x7.y, a1.y);
    }

    // Secondary: 4 edges.
    for (; i + 4 <= e; i += 4) {
        int c0 = __ldg(&col[i + 0]);
        int c1 = __ldg(&col[i + 1]);
        int c2 = __ldg(&col[i + 2]);
        int c3 = __ldg(&col[i + 3]);
        __half2 h0 = __ldg(&xh[(size_t)c0 * 32]);
        __half2 h1 = __ldg(&xh[(size_t)c1 * 32]);
        __half2 h2 = __ldg(&xh[(size_t)c2 * 32]);
        __half2 h3 = __ldg(&xh[(size_t)c3 * 32]);
        float v0 = __ldg(&vals[i + 0]);
        float v1 = __ldg(&vals[i + 1]);
        float v2 = __ldg(&vals[i + 2]);
        float v3 = __ldg(&vals[i + 3]);
        float2 x0 = __half22float2(h0);
        float2 x1 = __half22float2(h1);
        float2 x2 = __half22float2(h2);
        float2 x3 = __half22float2(h3);
        a0.x = fmaf(v0, x0.x, a0.x); a0.y = fmaf(v0, x0.y, a0.y);
        a1.x = fmaf(v1, x1.x, a1.x); a1.y = fmaf(v1, x1.y, a1.y);
        a0.x = fmaf(v2, x2.x, a0.x); a0.y = fmaf(v2, x2.y, a0.y);
        a1.x = fmaf(v3, x3.x, a1.x); a1.y = fmaf(v3, x3.y, a1.y);
    }

    // Tail: <=3 scalar edges.
    for (; i < e; i++) {
        int   c = __ldg(&col[i]);
        float v = __ldg(&vals[i]);
        float2 xv = __half22float2(__ldg(&xh[(size_t)c * 32]));
        a0.x = fmaf(v, xv.x, a0.x);
        a0.y = fmaf(v, xv.y, a0.y);
    }

    int deg = e - s;
    float inv = 1.0f / (float)(deg > 0 ? deg : 1);
    float2 o = make_float2((a0.x + a1.x) * inv, (a0.y + a1.y) * inv);

    *reinterpret_cast<float2*>(&out[(size_t)warp_id * D_FEAT + 2 * lane]) = o;
}

extern "C" void kernel_launch(void* const* d_in, const int* in_sizes, int n_in,
                              void* d_out, int out_size) {
    const float* x    = (const float*)d_in[0];
    const float* vals = (const float*)d_in[1];
    const int*   row  = (const int*)d_in[2];
    const int*   col  = (const int*)d_in[3];
    float* out = (float*)d_out;

    int n = in_sizes[0] / D_FEAT;   // 100000
    int E = in_sizes[1];            // 1200000

    {
        int n4 = n * D_FEAT / 4;                       // 1.6M float4s
        int builder_threads = (E + 3) / 4;             // 300k
        int builder_blocks = (builder_threads + PREP_THREADS - 1) / PREP_THREADS;
        prep_kernel<<<CONV_BLOCKS + builder_blocks, PREP_THREADS>>>(
            (const float4*)x, row, n4, n, E);
    }
    {
        int threads = 128;
        int rows_per_block = threads / 32;
        int blocks = (n + rows_per_block - 1) / rows_per_block;
        spmm_mean_warp_per_row<<<blocks, threads>>>(vals, col, out, n);
    }
}

// round 15
// speedup vs baseline: 1.1232x; 1.0109x over previous
#include <cuda_runtime.h>
#include <cuda_fp16.h>

#define D_FEAT 64
#define N_MAX 100000
#define CONV_BLOCKS 1184   // 148 SMs x 8
#define PREP_THREADS 256

__device__ int g_row_ptr[N_MAX + 1];
// fp16 staged x: N_MAX rows x 16 uint2 (= 32 half2 = 64 features). 12.8MB.
__device__ uint2 g_xh2[N_MAX * 16];

__device__ __forceinline__ unsigned pack_h2(float a, float b) {
    __half2 h = __floats2half2_rn(a, b);
    return *reinterpret_cast<unsigned*>(&h);
}

// Fused prep: blocks [0, CONV_BLOCKS) convert x fp32->fp16 (grid-stride,
// 8B stores); remaining blocks build row_ptr via boundary scatter.
__global__ void __launch_bounds__(PREP_THREADS)
prep_kernel(const float4* __restrict__ x4, const int* __restrict__ row,
            int n4, int n, int E) {
    if (blockIdx.x < CONV_BLOCKS) {
        int stride = CONV_BLOCKS * PREP_THREADS;
        for (int i = blockIdx.x * PREP_THREADS + threadIdx.x; i < n4; i += stride) {
            float4 v = __ldg(&x4[i]);
            uint2 p;
            p.x = pack_h2(v.x, v.y);
            p.y = pack_h2(v.z, v.w);
            g_xh2[i] = p;
        }
    } else {
        int t = (blockIdx.x - CONV_BLOCKS) * PREP_THREADS + threadIdx.x;
        int i = 4 * t;
        if (i >= E) return;

        int r0, r1, r2, r3;
        if (i + 3 < E) {
            int4 r4 = __ldg(reinterpret_cast<const int4*>(row + i));
            r0 = r4.x; r1 = r4.y; r2 = r4.z; r3 = r4.w;
        } else {
            r0 = __ldg(&row[i]);
            r1 = (i + 1 < E) ? __ldg(&row[i + 1]) : r0;
            r2 = (i + 2 < E) ? __ldg(&row[i + 2]) : r1;
            r3 = (i + 3 < E) ? __ldg(&row[i + 3]) : r2;
        }
        int prev = (i == 0) ? -1 : __ldg(&row[i - 1]);

        int rr[4] = {r0, r1, r2, r3};
#pragma unroll
        for (int k = 0; k < 4; k++) {
            if (i + k < E) {
                for (int r = prev + 1; r <= rr[k]; r++) g_row_ptr[r] = i + k;
                prev = rr[k];
            }
        }
        if (i + 4 >= E) {
            for (int r = prev + 1; r <= n; r++) g_row_ptr[r] = E;
        }
    }
}

// 8-edge macro chunk: loads cols, issues gathers; vals+FMA deferred by caller
// via the returned registers. Implemented inline below for clarity.

// SpMM: one warp per row, lane owns features {2l,2l+1} as ONE half2.
// 16-edge main loop as two staggered 8-edge half-batches: ~16 gathers
// outstanding per warp. fp32 accumulation.
__global__ void __launch_bounds__(128)
spmm_mean_warp_per_row(const float* __restrict__ vals,
                       const int* __restrict__ col,
                       float* __restrict__ out,
                       int n) {
    int warp_id = (blockIdx.x * blockDim.x + threadIdx.x) >> 5;
    int lane = threadIdx.x & 31;
    if (warp_id >= n) return;

    int s = g_row_ptr[warp_id];
    int e = g_row_ptr[warp_id + 1];

    const __half2* xh = reinterpret_cast<const __half2*>(g_xh2) + lane;
    float2 a0 = make_float2(0.f, 0.f);
    float2 a1 = make_float2(0.f, 0.f);

    int i = s;

    // Main loop: 16 edges = half-batch A (8) + half-batch B (8).
    for (; i + 16 <= e; i += 16) {
        // --- A: cols + gathers ---
        int cA0 = __ldg(&col[i + 0]);
        int cA1 = __ldg(&col[i + 1]);
        int cA2 = __ldg(&col[i + 2]);
        int cA3 = __ldg(&col[i + 3]);
        int cA4 = __ldg(&col[i + 4]);
        int cA5 = __ldg(&col[i + 5]);
        int cA6 = __ldg(&col[i + 6]);
        int cA7 = __ldg(&col[i + 7]);
        __half2 hA0 = __ldg(&xh[(size_t)cA0 * 32]);
        __half2 hA1 = __ldg(&xh[(size_t)cA1 * 32]);
        __half2 hA2 = __ldg(&xh[(size_t)cA2 * 32]);
        __half2 hA3 = __ldg(&xh[(size_t)cA3 * 32]);
        __half2 hA4 = __ldg(&xh[(size_t)cA4 * 32]);
        __half2 hA5 = __ldg(&xh[(size_t)cA5 * 32]);
        __half2 hA6 = __ldg(&xh[(size_t)cA6 * 32]);
        __half2 hA7 = __ldg(&xh[(size_t)cA7 * 32]);
        // --- B: cols + gathers (issued while A's gathers are in flight) ---
        int cB0 = __ldg(&col[i + 8]);
        int cB1 = __ldg(&col[i + 9]);
        int cB2 = __ldg(&col[i + 10]);
        int cB3 = __ldg(&col[i + 11]);
        int cB4 = __ldg(&col[i + 12]);
        int cB5 = __ldg(&col[i + 13]);
        int cB6 = __ldg(&col[i + 14]);
        int cB7 = __ldg(&col[i + 15]);
        __half2 hB0 = __ldg(&xh[(size_t)cB0 * 32]);
        __half2 hB1 = __ldg(&xh[(size_t)cB1 * 32]);
        __half2 hB2 = __ldg(&xh[(size_t)cB2 * 32]);
        __half2 hB3 = __ldg(&xh[(size_t)cB3 * 32]);
        __half2 hB4 = __ldg(&xh[(size_t)cB4 * 32]);
        __half2 hB5 = __ldg(&xh[(size_t)cB5 * 32]);
        __half2 hB6 = __ldg(&xh[(size_t)cB6 * 32]);
        __half2 hB7 = __ldg(&xh[(size_t)cB7 * 32]);

        // --- A: vals + FMAs (consume A gathers; B still in flight) ---
        float vA0 = __ldg(&vals[i + 0]);
        float vA1 = __ldg(&vals[i + 1]);
        float vA2 = __ldg(&vals[i + 2]);
        float vA3 = __ldg(&vals[i + 3]);
        float vA4 = __ldg(&vals[i + 4]);
        float vA5 = __ldg(&vals[i + 5]);
        float vA6 = __ldg(&vals[i + 6]);
        float vA7 = __ldg(&vals[i + 7]);
        {
            float2 x0 = __half22float2(hA0);
            float2 x1 = __half22float2(hA1);
            float2 x2 = __half22float2(hA2);
            float2 x3 = __half22float2(hA3);
            float2 x4 = __half22float2(hA4);
            float2 x5 = __half22float2(hA5);
            float2 x6 = __half22float2(hA6);
            float2 x7 = __half22float2(hA7);
            a0.x = fmaf(vA0, x0.x, a0.x); a0.y = fmaf(vA0, x0.y, a0.y);
            a1.x = fmaf(vA1, x1.x, a1.x); a1.y = fmaf(vA1, x1.y, a1.y);
            a0.x = fmaf(vA2, x2.x, a0.x); a0.y = fmaf(vA2, x2.y, a0.y);
            a1.x = fmaf(vA3, x3.x, a1.x); a1.y = fmaf(vA3, x3.y, a1.y);
            a0.x = fmaf(vA4, x4.x, a0.x); a0.y = fmaf(vA4, x4.y, a0.y);
            a1.x = fmaf(vA5, x5.x, a1.x); a1.y = fmaf(vA5, x5.y, a1.y);
            a0.x = fmaf(vA6, x6.x, a0.x); a0.y = fmaf(vA6, x6.y, a0.y);
            a1.x = fmaf(vA7, x7.x, a1.x); a1.y = fmaf(vA7, x7.y, a1.y);
        }
        // --- B: vals + FMAs ---
        float vB0 = __ldg(&vals[i + 8]);
        float vB1 = __ldg(&vals[i + 9]);
        float vB2 = __ldg(&vals[i + 10]);
        float vB3 = __ldg(&vals[i + 11]);
        float vB4 = __ldg(&vals[i + 12]);
        float vB5 = __ldg(&vals[i + 13]);
        float vB6 = __ldg(&vals[i + 14]);
        float vB7 = __ldg(&vals[i + 15]);
        {
            float2 x0 = __half22float2(hB0);
            float2 x1 = __half22float2(hB1);
            float2 x2 = __half22float2(hB2);
            float2 x3 = __half22float2(hB3);
            float2 x4 = __half22float2(hB4);
            float2 x5 = __half22float2(hB5);
            float2 x6 = __half22float2(hB6);
            float2 x7 = __half22float2(hB7);
            a0.x = fmaf(vB0, x0.x, a0.x); a0.y = fmaf(vB0, x0.y, a0.y);
            a1.x = fmaf(vB1, x1.x, a1.x); a1.y = fmaf(vB1, x1.y, a1.y);
            a0.x = fmaf(vB2, x2.x, a0.x); a0.y = fmaf(vB2, x2.y, a0.y);
            a1.x = fmaf(vB3, x3.x, a1.x); a1.y = fmaf(vB3, x3.y, a1.y);
            a0.x = fmaf(vB4, x4.x, a0.x); a0.y = fmaf(vB4, x4.y, a0.y);
            a1.x = fmaf(vB5, x5.x, a1.x); a1.y = fmaf(vB5, x5.y, a1.y);
            a0.x = fmaf(vB6, x6.x, a0.x); a0.y = fmaf(vB6, x6.y, a0.y);
            a1.x = fmaf(vB7, x7.x, a1.x); a1.y = fmaf(vB7, x7.y, a1.y);
        }
    }

    // 8-edge step.
    for (; i + 8 <= e; i += 8) {
        int c0 = __ldg(&col[i + 0]);
        int c1 = __ldg(&col[i + 1]);
        int c2 = __ldg(&col[i + 2]);
        int c3 = __ldg(&col[i + 3]);
        int c4 = __ldg(&col[i + 4]);
        int c5 = __ldg(&col[i + 5]);
        int c6 = __ldg(&col[i + 6]);
        int c7 = __ldg(&col[i + 7]);
        __half2 h0 = __ldg(&xh[(size_t)c0 * 32]);
        __half2 h1 = __ldg(&xh[(size_t)c1 * 32]);
        __half2 h2 = __ldg(&xh[(size_t)c2 * 32]);
        __half2 h3 = __ldg(&xh[(size_t)c3 * 32]);
        __half2 h4 = __ldg(&xh[(size_t)c4 * 32]);
        __half2 h5 = __ldg(&xh[(size_t)c5 * 32]);
        __half2 h6 = __ldg(&xh[(size_t)c6 * 32]);
        __half2 h7 = __ldg(&xh[(size_t)c7 * 32]);
        float v0 = __ldg(&vals[i + 0]);
        float v1 = __ldg(&vals[i + 1]);
        float v2 = __ldg(&vals[i + 2]);
        float v3 = __ldg(&vals[i + 3]);
        float v4 = __ldg(&vals[i + 4]);
        float v5 = __ldg(&vals[i + 5]);
        float v6 = __ldg(&vals[i + 6]);
        float v7 = __ldg(&vals[i + 7]);
        float2 x0 = __half22float2(h0);
        float2 x1 = __half22float2(h1);
        float2 x2 = __half22float2(h2);
        float2 x3 = __half22float2(h3);
        float2 x4 = __half22float2(h4);
        float2 x5 = __half22float2(h5);
        float2 x6 = __half22float2(h6);
        float2 x7 = __half22float2(h7);
        a0.x = fmaf(v0, x0.x, a0.x); a0.y = fmaf(v0, x0.y, a0.y);
        a1.x = fmaf(v1, x1.x, a1.x); a1.y = fmaf(v1, x1.y, a1.y);
        a0.x = fmaf(v2, x2.x, a0.x); a0.y = fmaf(v2, x2.y, a0.y);
        a1.x = fmaf(v3, x3.x, a1.x); a1.y = fmaf(v3, x3.y, a1.y);
        a0.x = fmaf(v4, x4.x, a0.x); a0.y = fmaf(v4, x4.y, a0.y);
        a1.x = fmaf(v5, x5.x, a1.x); a1.y = fmaf(v5, x5.y, a1.y);
        a0.x = fmaf(v6, x6.x, a0.x); a0.y = fmaf(v6, x6.y, a0.y);
        a1.x = fmaf(v7, x7.x, a1.x); a1.y = fmaf(v7, x7.y, a1.y);
    }

    // 4-edge step.
    for (; i + 4 <= e; i += 4) {
        int c0 = __ldg(&col[i + 0]);
        int c1 = __ldg(&col[i + 1]);
        int c2 = __ldg(&col[i + 2]);
        int c3 = __ldg(&col[i + 3]);
        __half2 h0 = __ldg(&xh[(size_t)c0 * 32]);
        __half2 h1 = __ldg(&xh[(size_t)c1 * 32]);
        __half2 h2 = __ldg(&xh[(size_t)c2 * 32]);
        __half2 h3 = __ldg(&xh[(size_t)c3 * 32]);
        float v0 = __ldg(&vals[i + 0]);
        float v1 = __ldg(&vals[i + 1]);
        float v2 = __ldg(&vals[i + 2]);
        float v3 = __ldg(&vals[i + 3]);
        float2 x0 = __half22float2(h0);
        float2 x1 = __half22float2(h1);
        float2 x2 = __half22float2(h2);
        float2 x3 = __half22float2(h3);
        a0.x = fmaf(v0, x0.x, a0.x); a0.y = fmaf(v0, x0.y, a0.y);
        a1.x = fmaf(v1, x1.x, a1.x); a1.y = fmaf(v1, x1.y, a1.y);
        a0.x = fmaf(v2, x2.x, a0.x); a0.y = fmaf(v2, x2.y, a0.y);
        a1.x = fmaf(v3, x3.x, a1.x); a1.y = fmaf(v3, x3.y, a1.y);
    }

    // Tail: <=3 scalar edges.
    for (; i < e; i++) {
        int   c = __ldg(&col[i]);
        float v = __ldg(&vals[i]);
        float2 xv = __half22float2(__ldg(&xh[(size_t)c * 32]));
        a0.x = fmaf(v, xv.x, a0.x);
        a0.y = fmaf(v, xv.y, a0.y);
    }

    int deg = e - s;
    float inv = 1.0f / (float)(deg > 0 ? deg : 1);
    float2 o = make_float2((a0.x + a1.x) * inv, (a0.y + a1.y) * inv);

    *reinterpret_cast<float2*>(&out[(size_t)warp_id * D_FEAT + 2 * lane]) = o;
}

extern "C" void kernel_launch(void* const* d_in, const int* in_sizes, int n_in,
                              void* d_out, int out_size) {
    const float* x    = (const float*)d_in[0];
    const float* vals = (const float*)d_in[1];
    const int*   row  = (const int*)d_in[2];
    const int*   col  = (const int*)d_in[3];
    float* out = (float*)d_out;

    int n = in_sizes[0] / D_FEAT;   // 100000
    int E = in_sizes[1];            // 1200000

    {
        int n4 = n * D_FEAT / 4;
        int builder_threads = (E + 3) / 4;
        int builder_blocks = (builder_threads + PREP_THREADS - 1) / PREP_THREADS;
        prep_kernel<<<CONV_BLOCKS + builder_blocks, PREP_THREADS>>>(
            (const float4*)x, row, n4, n, E);
    }
    {
        int threads = 128;
        int rows_per_block = threads / 32;
        int blocks = (n + rows_per_block - 1) / rows_per_block;
        spmm_mean_warp_per_row<<<blocks, threads>>>(vals, col, out, n);
    }
}